// round 6
// baseline (speedup 1.0000x reference)
#include <cuda_runtime.h>
#include <cuda_bf16.h>
#include <cstdint>

#define N 1024
#define D 2048
#define PARTS 8
#define SEGS 9
#define KDIM (SEGS*D)        // 18432
#define KSPLIT 4
#define KCHUNK (KDIM/KSPLIT) // 4608
#define BK 32
#define KITERS (KCHUNK/BK)   // 144
#define TILE 128
#define NTILES (N/TILE)      // 8
#define NPAIRS 36            // upper-triangle tile pairs
#define MARGIN 0.3f

// Scratch (no allocations allowed): R packed bf16, 4 K-split partial S, mining results.
__device__ __nv_bfloat16 g_R[(size_t)N * KDIM];       // 36 MB
__device__ float g_S[KSPLIT][(size_t)N * N];          // 16 MB
__device__ float g_ap[N];
__device__ float g_an[N];

// ---------------------------------------------------------------------------
// PTX helpers
// ---------------------------------------------------------------------------
__device__ __forceinline__ uint32_t smem_u32(const void* p) {
    return (uint32_t)__cvta_generic_to_shared(p);
}

__device__ __forceinline__ void cp16(void* smem, const void* g) {
    uint32_t s = smem_u32(smem);
    asm volatile("cp.async.cg.shared.global [%0], [%1], 16;\n" :: "r"(s), "l"(g));
}
#define CP_COMMIT() asm volatile("cp.async.commit_group;\n" ::: "memory")
#define CP_WAIT(n)  asm volatile("cp.async.wait_group %0;\n" :: "n"(n) : "memory")

__device__ __forceinline__ void ldm4(uint32_t* r, uint32_t addr) {
    asm volatile("ldmatrix.sync.aligned.m8n8.x4.shared.b16 {%0,%1,%2,%3}, [%4];\n"
                 : "=r"(r[0]), "=r"(r[1]), "=r"(r[2]), "=r"(r[3]) : "r"(addr));
}

__device__ __forceinline__ void mma16816(float* c, const uint32_t* a, uint32_t b0, uint32_t b1) {
    asm volatile(
        "mma.sync.aligned.m16n8k16.row.col.f32.bf16.bf16.f32 "
        "{%0,%1,%2,%3}, {%4,%5,%6,%7}, {%8,%9}, {%0,%1,%2,%3};\n"
        : "+f"(c[0]), "+f"(c[1]), "+f"(c[2]), "+f"(c[3])
        : "r"(a[0]), "r"(a[1]), "r"(a[2]), "r"(a[3]), "r"(b0), "r"(b1));
}

// ---------------------------------------------------------------------------
// K1: L2-normalize each 2048-dim segment; partial segments scaled by label.
// R[i] = [ ghat_i | l_{i,0}*phat_{i,0} | ... | l_{i,7}*phat_{i,7} ]   (bf16)
// ---------------------------------------------------------------------------
__global__ void pack_kernel(const float* __restrict__ gfeat,
                            const float* __restrict__ pfeat,
                            const float* __restrict__ plab) {
    int blk = blockIdx.x;            // 0 .. N*SEGS-1
    int i   = blk / SEGS;
    int seg = blk % SEGS;
    const float* src;
    float lab = 1.0f;
    if (seg == 0) {
        src = gfeat + (size_t)i * D;
    } else {
        src = pfeat + ((size_t)i * PARTS + (seg - 1)) * D;
        lab = plab[i * PARTS + (seg - 1)];
    }
    int t = threadIdx.x;             // 256 threads, 8 floats each
    const float4* s4 = (const float4*)src;
    float4 v0 = s4[t];
    float4 v1 = s4[t + 256];
    float ss = v0.x*v0.x + v0.y*v0.y + v0.z*v0.z + v0.w*v0.w
             + v1.x*v1.x + v1.y*v1.y + v1.z*v1.z + v1.w*v1.w;
    #pragma unroll
    for (int o = 16; o > 0; o >>= 1) ss += __shfl_xor_sync(0xffffffffu, ss, o);
    __shared__ float warp_ss[8];
    __shared__ float total;
    if ((t & 31) == 0) warp_ss[t >> 5] = ss;
    __syncthreads();
    if (t == 0) {
        float s = 0.f;
        #pragma unroll
        for (int w = 0; w < 8; w++) s += warp_ss[w];
        total = s;
    }
    __syncthreads();
    float scale = lab / (sqrtf(total) + 1e-12f);

    __nv_bfloat162* dst = (__nv_bfloat162*)(g_R + (size_t)i * KDIM + (size_t)seg * D);
    float2 p;
    p = make_float2(v0.x * scale, v0.y * scale); dst[2*t]           = __float22bfloat162_rn(p);
    p = make_float2(v0.z * scale, v0.w * scale); dst[2*t + 1]       = __float22bfloat162_rn(p);
    p = make_float2(v1.x * scale, v1.y * scale); dst[2*(t+256)]     = __float22bfloat162_rn(p);
    p = make_float2(v1.z * scale, v1.w * scale); dst[2*(t+256) + 1] = __float22bfloat162_rn(p);
}

// ---------------------------------------------------------------------------
// K2: S = R R^T, upper-triangle 128x128 tiles, 4-way K-split.
// 256 threads = 8 warps (2 x 4), warp tile 64x32, mma.sync m16n8k16 bf16.
// ---------------------------------------------------------------------------
__global__ __launch_bounds__(256, 1)
void gemm_kernel() {
    int tile  = blockIdx.x % NPAIRS;
    int chunk = blockIdx.x / NPAIRS;
    int bi = 0, tt = tile;
    while (tt >= NTILES - bi) { tt -= NTILES - bi; bi++; }
    int bj = bi + tt;

    const __nv_bfloat16* Abase = g_R + (size_t)(bi * TILE) * KDIM + (size_t)chunk * KCHUNK;
    const __nv_bfloat16* Bbase = g_R + (size_t)(bj * TILE) * KDIM + (size_t)chunk * KCHUNK;

    __shared__ __nv_bfloat16 As[2][TILE][BK + 8];   // +8 pad: conflict-free ldmatrix
    __shared__ __nv_bfloat16 Bs[2][TILE][BK + 8];

    int tid  = threadIdx.x;
    int lane = tid & 31;
    int warp = tid >> 5;
    int wm   = warp >> 2;    // 0..1
    int wn   = warp & 3;     // 0..3

    float acc[4][4][4];
    #pragma unroll
    for (int mi = 0; mi < 4; mi++)
        #pragma unroll
        for (int ni = 0; ni < 4; ni++)
            #pragma unroll
            for (int e = 0; e < 4; e++) acc[mi][ni][e] = 0.f;

    int lr = tid >> 2;           // 0..63
    int lc = (tid & 3) * 8;      // 0,8,16,24

    auto load_tile = [&](int it, int buf) {
        const __nv_bfloat16* ga = Abase + (size_t)lr * KDIM + (size_t)it * BK + lc;
        const __nv_bfloat16* gb = Bbase + (size_t)lr * KDIM + (size_t)it * BK + lc;
        cp16(&As[buf][lr][lc],      ga);
        cp16(&As[buf][lr + 64][lc], ga + (size_t)64 * KDIM);
        cp16(&Bs[buf][lr][lc],      gb);
        cp16(&Bs[buf][lr + 64][lc], gb + (size_t)64 * KDIM);
    };

    load_tile(0, 0);
    CP_COMMIT();

    int buf = 0;
    for (int it = 0; it < KITERS; it++) {
        if (it + 1 < KITERS) {
            load_tile(it + 1, buf ^ 1);
            CP_COMMIT();
            CP_WAIT(1);          // group for `it` complete
        } else {
            CP_WAIT(0);
        }
        __syncthreads();

        #pragma unroll
        for (int ks = 0; ks < BK; ks += 16) {
            uint32_t af[4][4];
            #pragma unroll
            for (int mi = 0; mi < 4; mi++) {
                int r = wm * 64 + mi * 16 + (lane & 15);
                int c = ks + ((lane >> 4) << 3);
                ldm4(af[mi], smem_u32(&As[buf][r][c]));
            }
            uint32_t bfr[2][4];
            #pragma unroll
            for (int nb = 0; nb < 2; nb++) {
                int g8 = lane >> 3;                       // 0..3
                int r  = wn * 32 + nb * 16 + ((g8 & 2) ? 8 : 0) + (lane & 7);
                int c  = ks + ((g8 & 1) ? 8 : 0);
                ldm4(bfr[nb], smem_u32(&Bs[buf][r][c]));
            }
            #pragma unroll
            for (int mi = 0; mi < 4; mi++)
                #pragma unroll
                for (int ni = 0; ni < 4; ni++)
                    mma16816(acc[mi][ni], af[mi],
                             bfr[ni >> 1][(ni & 1) * 2],
                             bfr[ni >> 1][(ni & 1) * 2 + 1]);
        }
        __syncthreads();
        buf ^= 1;
    }

    // Write partial S (upper triangle region only; no init/atomics needed).
    float* Sc = g_S[chunk];
    int rowbase = bi * TILE + wm * 64;
    int colbase = bj * TILE + wn * 32;
    #pragma unroll
    for (int mi = 0; mi < 4; mi++) {
        int r0 = rowbase + mi * 16 + (lane >> 2);
        #pragma unroll
        for (int ni = 0; ni < 4; ni++) {
            int c0 = colbase + ni * 8 + (lane & 3) * 2;
            *(float2*)&Sc[(size_t)r0 * N + c0]       = make_float2(acc[mi][ni][0], acc[mi][ni][1]);
            *(float2*)&Sc[(size_t)(r0 + 8) * N + c0] = make_float2(acc[mi][ni][2], acc[mi][ni][3]);
        }
    }
}

// ---------------------------------------------------------------------------
// K3: per-row hard mining.  dist_ij = 0.5 - S_ij / (2*(O_ij+1)),
// O_ij = L_i . L_j (8-dim part labels). Symmetric S read via (min,max) index.
// global_labels dtype is detected at runtime: JAX with x64 disabled makes
// .astype(jnp.int64) a silent no-op (int32). If the buffer really is int64
// (values < 64), all odd 32-bit words of the first 1024 words are zero; for
// int32 they are 512 random labels in 0..63 — distinguishable with certainty.
// Only the first 1024 words are touched (in-bounds for both layouts).
// ---------------------------------------------------------------------------
__global__ void mine_kernel(const float* __restrict__ plab,
                            const void* __restrict__ glab_raw) {
    int i = blockIdx.x;
    int t = threadIdx.x;   // 128

    __shared__ int slab[N];
    __shared__ int is64_s;

    if (t == 0) {
        const unsigned* w = (const unsigned*)glab_raw;
        unsigned acc = 0;
        for (int q = 1; q < 1024; q += 2) acc |= w[q];
        is64_s = (acc == 0) ? 1 : 0;
    }
    __syncthreads();
    if (is64_s) {
        const long long* g64 = (const long long*)glab_raw;
        for (int j = t; j < N; j += 128) slab[j] = (int)g64[j];
    } else {
        const int* g32 = (const int*)glab_raw;
        for (int j = t; j < N; j += 128) slab[j] = g32[j];
    }
    __syncthreads();

    int gi = slab[i];
    float Li[8];
    #pragma unroll
    for (int p = 0; p < 8; p++) Li[p] = plab[i * 8 + p];

    float mx = -3.4e38f, mn = 3.4e38f;
    for (int j = t; j < N; j += 128) {
        size_t idx = (i <= j) ? ((size_t)i * N + j) : ((size_t)j * N + i);
        float S = g_S[0][idx] + g_S[1][idx] + g_S[2][idx] + g_S[3][idx];
        const float4* Lj4 = (const float4*)&plab[j * 8];
        float4 a = Lj4[0], b = Lj4[1];
        float O = Li[0]*a.x + Li[1]*a.y + Li[2]*a.z + Li[3]*a.w
                + Li[4]*b.x + Li[5]*b.y + Li[6]*b.z + Li[7]*b.w;
        float dist = 0.5f - S / (2.0f * (O + 1.0f));
        if (slab[j] == gi) mx = fmaxf(mx, dist);
        else               mn = fminf(mn, dist);
    }
    #pragma unroll
    for (int o = 16; o > 0; o >>= 1) {
        mx = fmaxf(mx, __shfl_xor_sync(0xffffffffu, mx, o));
        mn = fminf(mn, __shfl_xor_sync(0xffffffffu, mn, o));
    }
    __shared__ float smx[4], smn[4];
    if ((t & 31) == 0) { smx[t >> 5] = mx; smn[t >> 5] = mn; }
    __syncthreads();
    if (t == 0) {
        #pragma unroll
        for (int w = 1; w < 4; w++) {
            smx[0] = fmaxf(smx[0], smx[w]);
            smn[0] = fminf(smn[0], smn[w]);
        }
        g_ap[i] = smx[0];
        g_an[i] = smn[0];
    }
}

// ---------------------------------------------------------------------------
// K4: loss = mean(relu(ap - an + margin))
// ---------------------------------------------------------------------------
__global__ void loss_kernel(float* __restrict__ out) {
    int t = threadIdx.x;   // 256
    float s = 0.f;
    for (int i = t; i < N; i += 256)
        s += fmaxf(g_ap[i] - g_an[i] + MARGIN, 0.f);
    #pragma unroll
    for (int o = 16; o > 0; o >>= 1) s += __shfl_xor_sync(0xffffffffu, s, o);
    __shared__ float ws[8];
    if ((t & 31) == 0) ws[t >> 5] = s;
    __syncthreads();
    if (t == 0) {
        float tot = 0.f;
        #pragma unroll
        for (int w = 0; w < 8; w++) tot += ws[w];
        out[0] = tot / (float)N;
    }
}

// ---------------------------------------------------------------------------
extern "C" void kernel_launch(void* const* d_in, const int* in_sizes, int n_in,
                              void* d_out, int out_size) {
    const float* gfeat = (const float*)d_in[0];      // [1024, 2048]
    const float* pfeat = (const float*)d_in[1];      // [1024, 8, 2048]
    const float* plab  = (const float*)d_in[2];      // [1024, 8]
    const void*  glab  = d_in[3];                    // [1024] int32 or int64

    pack_kernel<<<N * SEGS, 256>>>(gfeat, pfeat, plab);
    gemm_kernel<<<NPAIRS * KSPLIT, 256>>>();
    mine_kernel<<<N, 128>>>(plab, glab);
    loss_kernel<<<1, 256>>>((float*)d_out);
}

// round 10
// speedup vs baseline: 1.3108x; 1.3108x over previous
#include <cuda_runtime.h>
#include <cuda_bf16.h>
#include <cstdint>

#define N 1024
#define D 2048
#define PARTS 8
#define SEGS 9
#define KDIM (SEGS*D)           // 18432
#define KSPLIT 4
#define KCHUNK (KDIM/KSPLIT)    // 4608
#define TILE 128
#define NTILES (N/TILE)         // 8
#define NPAIRS 36
#define MARGIN 0.3f

#define BKG 64                  // K elems per block (=> 128B rows, SW128 atom)
#define KB_PER_TILE (KDIM/BKG)  // 288
#define GK_ITERS (KCHUNK/BKG)   // 72 stages per CTA
#define STAGES 6
#define TILE_B 16384            // one 128x64 bf16 block
#define STAGE_B (2*TILE_B)      // A + B per stage

// Scratch: R packed bf16 (tile-blocked, pre-swizzled), K-split partial S, mining results.
__device__ __align__(1024) __nv_bfloat16 g_R[(size_t)N * KDIM]; // 36 MB
__device__ float g_S[KSPLIT][(size_t)N * N];                    // 16 MB
__device__ float g_ap[N];
__device__ float g_an[N];
__device__ int   g_ticket;     // zero-init; reset by last mine block each launch

// ---------------------------------------------------------------------------
// PTX helpers (all sm_90-level: no 'a'-suffix features)
// ---------------------------------------------------------------------------
__device__ __forceinline__ uint32_t smem_u32(const void* p) {
    return (uint32_t)__cvta_generic_to_shared(p);
}

__device__ __forceinline__ void bulkcp(uint32_t smem, const void* g, uint32_t bytes, uint32_t mbar) {
    asm volatile(
        "cp.async.bulk.shared::cta.global.mbarrier::complete_tx::bytes [%0], [%1], %2, [%3];"
        :: "r"(smem), "l"(g), "r"(bytes), "r"(mbar) : "memory");
}
__device__ __forceinline__ void mbar_init(uint32_t m, uint32_t cnt) {
    asm volatile("mbarrier.init.shared.b64 [%0], %1;" :: "r"(m), "r"(cnt) : "memory");
}
__device__ __forceinline__ void mbar_expect_tx(uint32_t m, uint32_t bytes) {
    asm volatile("mbarrier.arrive.expect_tx.shared.b64 _, [%0], %1;" :: "r"(m), "r"(bytes) : "memory");
}
__device__ __forceinline__ void mbar_wait(uint32_t m, uint32_t parity) {
    uint32_t done;
    asm volatile(
        "{\n\t.reg .pred p;\n\t"
        "mbarrier.try_wait.parity.acquire.cta.shared::cta.b64 p, [%1], %2;\n\t"
        "selp.b32 %0, 1, 0, p;\n\t}"
        : "=r"(done) : "r"(m), "r"(parity) : "memory");
    while (!done) {
        asm volatile(
            "{\n\t.reg .pred p;\n\t"
            "mbarrier.try_wait.parity.acquire.cta.shared::cta.b64 p, [%1], %2, 0x989680;\n\t"
            "selp.b32 %0, 1, 0, p;\n\t}"
            : "=r"(done) : "r"(m), "r"(parity) : "memory");
    }
}
#define FENCE_PROXY_ASYNC() asm volatile("fence.proxy.async.shared::cta;" ::: "memory")

__device__ __forceinline__ void ldm4(uint32_t* r, uint32_t addr) {
    asm volatile("ldmatrix.sync.aligned.m8n8.x4.shared.b16 {%0,%1,%2,%3}, [%4];\n"
                 : "=r"(r[0]), "=r"(r[1]), "=r"(r[2]), "=r"(r[3]) : "r"(addr));
}
__device__ __forceinline__ void mma16816(float* c, const uint32_t* a, uint32_t b0, uint32_t b1) {
    asm volatile(
        "mma.sync.aligned.m16n8k16.row.col.f32.bf16.bf16.f32 "
        "{%0,%1,%2,%3}, {%4,%5,%6,%7}, {%8,%9}, {%0,%1,%2,%3};\n"
        : "+f"(c[0]), "+f"(c[1]), "+f"(c[2]), "+f"(c[3])
        : "r"(a[0]), "r"(a[1]), "r"(a[2]), "r"(a[3]), "r"(b0), "r"(b1));
}

// ---------------------------------------------------------------------------
// K1: normalize/scale and pack into tile-blocked, pre-SW128-swizzled layout.
// Block (tile=row/128, kb=K/64) is 16KB: 128 rows x 128B. Within a block,
// byte (r, c[bf16]) lands at  (r*128 + c*2) ^ (((r*128+c*2)>>3)&0x70),
// i.e. 16B-granule g=c/8 goes to granule g^(r&7).
// ---------------------------------------------------------------------------
__global__ void pack_kernel(const float* __restrict__ gfeat,
                            const float* __restrict__ pfeat,
                            const float* __restrict__ plab) {
    int blk = blockIdx.x;            // 0 .. N*SEGS-1
    int i   = blk / SEGS;
    int seg = blk % SEGS;
    const float* src;
    float lab = 1.0f;
    if (seg == 0) {
        src = gfeat + (size_t)i * D;
    } else {
        src = pfeat + ((size_t)i * PARTS + (seg - 1)) * D;
        lab = plab[i * PARTS + (seg - 1)];
    }
    int t = threadIdx.x;             // 256 threads, 8 floats each
    const float4* s4 = (const float4*)src;
    float4 v0 = s4[t];
    float4 v1 = s4[t + 256];
    float ss = v0.x*v0.x + v0.y*v0.y + v0.z*v0.z + v0.w*v0.w
             + v1.x*v1.x + v1.y*v1.y + v1.z*v1.z + v1.w*v1.w;
    #pragma unroll
    for (int o = 16; o > 0; o >>= 1) ss += __shfl_xor_sync(0xffffffffu, ss, o);
    __shared__ float warp_ss[8];
    __shared__ float total;
    if ((t & 31) == 0) warp_ss[t >> 5] = ss;
    __syncthreads();
    if (t == 0) {
        float s = 0.f;
        #pragma unroll
        for (int w = 0; w < 8; w++) s += warp_ss[w];
        total = s;
    }
    __syncthreads();
    float scale = lab / (sqrtf(total) + 1e-12f);

    int tile = i >> 7;
    int r    = i & 127;
    char* Rb = (char*)g_R;

    auto put = [&](int P, float a, float b) {   // P = bf16-pair index within row segment
        int c0  = seg * D + 2 * P;              // global K column (even)
        int kbg = c0 >> 6;
        int c   = c0 & 63;
        uint32_t inner = (uint32_t)r * 128 + (uint32_t)c * 2;
        inner ^= ((inner >> 3) & 0x70);         // SW128 pre-swizzle
        __nv_bfloat162 v = __float22bfloat162_rn(make_float2(a, b));
        *(__nv_bfloat162*)(Rb + (size_t)(tile * KB_PER_TILE + kbg) * TILE_B + inner) = v;
    };
    put(2*t,           v0.x*scale, v0.y*scale);
    put(2*t+1,         v0.z*scale, v0.w*scale);
    put(2*(t+256),     v1.x*scale, v1.y*scale);
    put(2*(t+256)+1,   v1.z*scale, v1.w*scale);
}

// ---------------------------------------------------------------------------
// K2: S = R R^T. cp.async.bulk (2 x 16KB per stage, single thread) feeds a
// 6-stage mbarrier ring; 8 warps of mma.sync m16n8k16 consume (warp tile 64x32).
// 36 upper-triangle pairs x 4 K-splits = 144 CTAs (one wave).
// ---------------------------------------------------------------------------
__global__ __launch_bounds__(256, 1)
void gemm_kernel() {
    extern __shared__ char dsm[];
    __shared__ __align__(8) unsigned long long bar_full[STAGES];

    uint32_t sbase = (smem_u32(dsm) + 1023u) & ~1023u;

    int tid  = threadIdx.x;
    int lane = tid & 31;
    int warp = tid >> 5;
    int wm   = warp >> 2;    // 0..1
    int wn   = warp & 3;     // 0..3

    int tileid = blockIdx.x % NPAIRS;
    int chunk  = blockIdx.x / NPAIRS;
    int bi = 0, tt = tileid;
    while (tt >= NTILES - bi) { tt -= NTILES - bi; bi++; }
    int bj = bi + tt;

    const char* Rb = (const char*)g_R;
    size_t abase = ((size_t)bi * KB_PER_TILE + (size_t)chunk * GK_ITERS) * TILE_B;
    size_t bbase = ((size_t)bj * KB_PER_TILE + (size_t)chunk * GK_ITERS) * TILE_B;

    if (tid == 0) {
        #pragma unroll
        for (int s = 0; s < STAGES; s++) mbar_init(smem_u32(&bar_full[s]), 1);
        FENCE_PROXY_ASYNC();
    }
    __syncthreads();

    if (tid == 0) {
        #pragma unroll
        for (int s = 0; s < STAGES; s++) {     // prologue: fill all stages
            uint32_t sb = sbase + s * STAGE_B;
            uint32_t fb = smem_u32(&bar_full[s]);
            mbar_expect_tx(fb, STAGE_B);
            bulkcp(sb,          Rb + abase + (size_t)s * TILE_B, TILE_B, fb);
            bulkcp(sb + TILE_B, Rb + bbase + (size_t)s * TILE_B, TILE_B, fb);
        }
    }

    float acc[4][4][4];
    #pragma unroll
    for (int mi = 0; mi < 4; mi++)
        #pragma unroll
        for (int ni = 0; ni < 4; ni++)
            #pragma unroll
            for (int e = 0; e < 4; e++) acc[mi][ni][e] = 0.f;

    for (int it = 0; it < GK_ITERS; it++) {
        int s = it % STAGES;
        mbar_wait(smem_u32(&bar_full[s]), (it / STAGES) & 1);
        uint32_t stA = sbase + s * STAGE_B;
        uint32_t stB = stA + TILE_B;

        #pragma unroll
        for (int ks = 0; ks < BKG; ks += 16) {
            uint32_t af[4][4];
            #pragma unroll
            for (int mi = 0; mi < 4; mi++) {
                int r = wm * 64 + mi * 16 + (lane & 15);
                int g = (ks >> 3) + (lane >> 4);
                ldm4(af[mi], stA + r * 128 + ((g ^ (r & 7)) << 4));
            }
            uint32_t bfr[2][4];
            #pragma unroll
            for (int nb = 0; nb < 2; nb++) {
                int g8 = lane >> 3;
                int r  = wn * 32 + nb * 16 + ((g8 & 2) ? 8 : 0) + (lane & 7);
                int g  = (ks >> 3) + (g8 & 1);
                ldm4(bfr[nb], stB + r * 128 + ((g ^ (r & 7)) << 4));
            }
            #pragma unroll
            for (int mi = 0; mi < 4; mi++)
                #pragma unroll
                for (int ni = 0; ni < 4; ni++)
                    mma16816(acc[mi][ni], af[mi],
                             bfr[ni >> 1][(ni & 1) * 2],
                             bfr[ni >> 1][(ni & 1) * 2 + 1]);
        }
        __syncthreads();                       // all reads of stage s done
        int ld = it + STAGES;
        if (tid == 0 && ld < GK_ITERS) {       // refill just-freed slot
            uint32_t sb = sbase + s * STAGE_B;
            uint32_t fb = smem_u32(&bar_full[s]);
            mbar_expect_tx(fb, STAGE_B);
            bulkcp(sb,          Rb + abase + (size_t)ld * TILE_B, TILE_B, fb);
            bulkcp(sb + TILE_B, Rb + bbase + (size_t)ld * TILE_B, TILE_B, fb);
        }
    }

    // Epilogue: write partial S (upper triangle region only).
    float* Sc = g_S[chunk];
    int rowbase = bi * TILE + wm * 64;
    int colbase = bj * TILE + wn * 32;
    #pragma unroll
    for (int mi = 0; mi < 4; mi++) {
        int r0 = rowbase + mi * 16 + (lane >> 2);
        #pragma unroll
        for (int ni = 0; ni < 4; ni++) {
            int c0 = colbase + ni * 8 + (lane & 3) * 2;
            *(float2*)&Sc[(size_t)r0 * N + c0]       = make_float2(acc[mi][ni][0], acc[mi][ni][1]);
            *(float2*)&Sc[(size_t)(r0 + 8) * N + c0] = make_float2(acc[mi][ni][2], acc[mi][ni][3]);
        }
    }
}

// ---------------------------------------------------------------------------
// K3 (fused mine+loss): dist_ij = 0.5 - S_ij / (2*(O_ij+1)); hardest pos/neg
// per row; last block (ticket) reduces the loss and resets the ticket.
// Runtime dtype detection for global_labels (int32 vs int64), as before.
// ---------------------------------------------------------------------------
__global__ void mine_kernel(const float* __restrict__ plab,
                            const void* __restrict__ glab_raw,
                            float* __restrict__ out) {
    int i = blockIdx.x;
    int t = threadIdx.x;   // 128

    __shared__ int slab[N];
    __shared__ int is64_s;

    if (t == 0) {
        const unsigned* w = (const unsigned*)glab_raw;
        unsigned acc = 0;
        for (int q = 1; q < 1024; q += 2) acc |= w[q];
        is64_s = (acc == 0) ? 1 : 0;
    }
    __syncthreads();
    if (is64_s) {
        const long long* g64 = (const long long*)glab_raw;
        for (int j = t; j < N; j += 128) slab[j] = (int)g64[j];
    } else {
        const int* g32 = (const int*)glab_raw;
        for (int j = t; j < N; j += 128) slab[j] = g32[j];
    }
    __syncthreads();

    int gi = slab[i];
    float Li[8];
    #pragma unroll
    for (int p = 0; p < 8; p++) Li[p] = plab[i * 8 + p];

    float mx = -3.4e38f, mn = 3.4e38f;
    for (int j = t; j < N; j += 128) {
        size_t idx = (i <= j) ? ((size_t)i * N + j) : ((size_t)j * N + i);
        float S = g_S[0][idx] + g_S[1][idx] + g_S[2][idx] + g_S[3][idx];
        const float4* Lj4 = (const float4*)&plab[j * 8];
        float4 a = Lj4[0], b = Lj4[1];
        float O = Li[0]*a.x + Li[1]*a.y + Li[2]*a.z + Li[3]*a.w
                + Li[4]*b.x + Li[5]*b.y + Li[6]*b.z + Li[7]*b.w;
        float dist = 0.5f - S / (2.0f * (O + 1.0f));
        if (slab[j] == gi) mx = fmaxf(mx, dist);
        else               mn = fminf(mn, dist);
    }
    #pragma unroll
    for (int o = 16; o > 0; o >>= 1) {
        mx = fmaxf(mx, __shfl_xor_sync(0xffffffffu, mx, o));
        mn = fminf(mn, __shfl_xor_sync(0xffffffffu, mn, o));
    }
    __shared__ float smx[4], smn[4];
    __shared__ int   last_s;
    if ((t & 31) == 0) { smx[t >> 5] = mx; smn[t >> 5] = mn; }
    __syncthreads();
    if (t == 0) {
        #pragma unroll
        for (int w = 1; w < 4; w++) {
            smx[0] = fmaxf(smx[0], smx[w]);
            smn[0] = fminf(smn[0], smn[w]);
        }
        g_ap[i] = smx[0];
        g_an[i] = smn[0];
        __threadfence();
        last_s = (atomicAdd(&g_ticket, 1) == N - 1);
    }
    __syncthreads();
    if (last_s) {
        float s = 0.f;
        for (int j = t; j < N; j += 128)
            s += fmaxf(g_ap[j] - g_an[j] + MARGIN, 0.f);
        #pragma unroll
        for (int o = 16; o > 0; o >>= 1) s += __shfl_xor_sync(0xffffffffu, s, o);
        __shared__ float ws[4];
        if ((t & 31) == 0) ws[t >> 5] = s;
        __syncthreads();
        if (t == 0) {
            float tot = ws[0] + ws[1] + ws[2] + ws[3];
            out[0] = tot / (float)N;
            g_ticket = 0;            // reset for next (graph-replayed) launch
        }
    }
}

// ---------------------------------------------------------------------------
extern "C" void kernel_launch(void* const* d_in, const int* in_sizes, int n_in,
                              void* d_out, int out_size) {
    const float* gfeat = (const float*)d_in[0];      // [1024, 2048]
    const float* pfeat = (const float*)d_in[1];      // [1024, 8, 2048]
    const float* plab  = (const float*)d_in[2];      // [1024, 8]
    const void*  glab  = d_in[3];                    // [1024] int32 or int64

    static bool attr_set = false;
    if (!attr_set) {
        cudaFuncSetAttribute(gemm_kernel,
                             cudaFuncAttributeMaxDynamicSharedMemorySize,
                             STAGES * STAGE_B + 1024);
        attr_set = true;
    }

    pack_kernel<<<N * SEGS, 256>>>(gfeat, pfeat, plab);
    gemm_kernel<<<NPAIRS * KSPLIT, 256, STAGES * STAGE_B + 1024>>>();
    mine_kernel<<<N, 128>>>(plab, glab, (float*)d_out);
}